// round 3
// baseline (speedup 1.0000x reference)
#include <cuda_runtime.h>
#include <stdint.h>

// ============================================================================
// ControlPointBetaNoise — exact re-implementation of the JAX reference.
// R3: fast-path restructure. The Marsaglia–Tsang accept path (>92% of
// samples) is now straight-line with lazy computation of the rejection-only
// threefry calls (nk / nxt): 18 -> 14 threefry evals per element. Both gamma
// samples' fast paths sit in one scope so their serial TF chains interleave.
// Rare rejections replay deterministically through a __noinline__ slow loop.
// ============================================================================

#define PARTITIONABLE 1

static const unsigned B_ = 32, C_ = 3, H_ = 512, W_ = 512;
static const unsigned PIX_PER_IMG = H_ * W_;              // 262144

struct U2 { uint32_t a, b; };

__host__ __device__ __forceinline__ uint32_t rotl32(uint32_t x, int r) {
#ifdef __CUDA_ARCH__
  return __funnelshift_l(x, x, r);
#else
  return (x << r) | (x >> (32 - r));
#endif
}

// threefry2x32, 20 rounds — matches jax._src.prng.threefry2x32 exactly.
__host__ __device__ __forceinline__ U2 tf2x32(uint32_t k0, uint32_t k1,
                                              uint32_t x0, uint32_t x1) {
  uint32_t ks2 = k0 ^ k1 ^ 0x1BD11BDAu;
  x0 += k0; x1 += k1;
#define TF_RND(r) { x0 += x1; x1 = rotl32(x1, (r)); x1 ^= x0; }
  TF_RND(13) TF_RND(15) TF_RND(26) TF_RND(6)
  x0 += k1;  x1 += ks2 + 1u;
  TF_RND(17) TF_RND(29) TF_RND(16) TF_RND(24)
  x0 += ks2; x1 += k0 + 2u;
  TF_RND(13) TF_RND(15) TF_RND(26) TF_RND(6)
  x0 += k0;  x1 += k1 + 3u;
  TF_RND(17) TF_RND(29) TF_RND(16) TF_RND(24)
  x0 += k1;  x1 += ks2 + 4u;
  TF_RND(13) TF_RND(15) TF_RND(26) TF_RND(6)
  x0 += ks2; x1 += k0 + 5u;
#undef TF_RND
  return U2{x0, x1};
}

// scalar-shape random_bits(key, 32, ())
__device__ __forceinline__ uint32_t bits_scalar(uint32_t k0, uint32_t k1) {
  U2 r = tf2x32(k0, k1, 0u, 0u);
  return r.a ^ r.b;
}

// uniform [0,1): bitcast((bits>>9)|0x3f800000) - 1.0  (matches jax._uniform)
__device__ __forceinline__ float u01_from_bits(uint32_t bits) {
  return __uint_as_float((bits >> 9) | 0x3F800000u) - 1.0f;
}

// XLA f32 erf_inv (Giles polynomial) — what lax.erf_inv lowers to.
__device__ __forceinline__ float erfinv_f32(float x) {
  float w = -log1pf(-x * x);
  float p;
  if (w < 5.0f) {
    w -= 2.5f;
    p = 2.81022636e-08f;
    p = fmaf(p, w, 3.43273939e-07f);
    p = fmaf(p, w, -3.5233877e-06f);
    p = fmaf(p, w, -4.39150654e-06f);
    p = fmaf(p, w, 0.00021858087f);
    p = fmaf(p, w, -0.00125372503f);
    p = fmaf(p, w, -0.00417768164f);
    p = fmaf(p, w, 0.246640727f);
    p = fmaf(p, w, 1.50140941f);
  } else {
    w = sqrtf(w) - 3.0f;
    p = -0.000200214257f;
    p = fmaf(p, w, 0.000100950558f);
    p = fmaf(p, w, 0.00134934322f);
    p = fmaf(p, w, -0.00367342844f);
    p = fmaf(p, w, 0.00573950773f);
    p = fmaf(p, w, -0.0076224613f);
    p = fmaf(p, w, 0.00943887047f);
    p = fmaf(p, w, 1.00167406f);
    p = fmaf(p, w, 2.83297682f);
  }
  return p * x;
}

// jax.random.normal: u = uniform(key, lo=nextafter(-1,0), hi=1); sqrt(2)*erfinv(u)
__device__ __forceinline__ float normal_from_key(uint32_t k0, uint32_t k1) {
  uint32_t bits = bits_scalar(k0, k1);
  float f = u01_from_bits(bits);
  const float LO = __uint_as_float(0xBF7FFFFFu);  // nextafter(-1,0)
  float u = fmaxf(LO, f * 2.0f + LO);
  return 1.41421356237f * erfinv_f32(u);
}

// ---------------------------------------------------------------------------
// Slow path: full Marsaglia–Tsang rejection loop starting from loop key kl.
// Called only for samples whose first straight-line attempt failed (~5-8%).
// Bit-identical replay of the key chain. Returns V of the accepted draw.
// ---------------------------------------------------------------------------
__device__ __noinline__ float gamma_slow(uint32_t kl0, uint32_t kl1,
                                         float d, float c) {
  for (;;) {
    U2 xk = tf2x32(kl0, kl1, 0u, 1u);
    U2 Uk = tf2x32(kl0, kl1, 0u, 2u);
    uint32_t xk0 = xk.a, xk1 = xk.b;
    float x, v;
    for (;;) {
      U2 sub = tf2x32(xk0, xk1, 0u, 1u);
      x = normal_from_key(sub.a, sub.b);
      v = 1.0f + c * x;
      if (v > 0.0f) break;
      U2 nxt = tf2x32(xk0, xk1, 0u, 0u);   // lazily advanced inner key
      xk0 = nxt.a; xk1 = nxt.b;
    }
    float X = x * x;
    float V = (v * v) * v;
    float U = u01_from_bits(bits_scalar(Uk.a, Uk.b));
    bool rej = (U >= 1.0f - 0.0331f * (X * X)) &&
               (logf(U) >= 0.5f * X + d * (1.0f - V + logf(V)));
    if (!rej) return V;
    U2 nk = tf2x32(kl0, kl1, 0u, 0u);      // lazily advanced outer key
    kl0 = nk.a; kl1 = nk.b;
  }
}

// ---------------------------------------------------------------------------
// Bicubic weight table: jax.image.resize "bicubic" (Keys a=-0.5, renormalized,
// half-pixel sampling). Identical for H and W (8 -> 512).
// ---------------------------------------------------------------------------
__device__ float g_w[512][8];

__global__ void weights_kernel() {
  int j = threadIdx.x;  // 0..511
  float s = (j + 0.5f) * (1.0f / 64.0f) - 0.5f;
  float w[8]; float sum = 0.0f;
#pragma unroll
  for (int i = 0; i < 8; i++) {
    float x = fabsf(s - (float)i);
    float out = ((1.5f * x - 2.5f) * x) * x + 1.0f;
    if (x >= 1.0f) out = ((-0.5f * x + 2.5f) * x - 4.0f) * x + 2.0f;
    if (x >= 2.0f) out = 0.0f;
    w[i] = out; sum += out;
  }
#pragma unroll
  for (int i = 0; i < 8; i++) g_w[j][i] = w[i] / sum;
}

// ---------------------------------------------------------------------------
// Main kernel: one thread per output pixel.
// ---------------------------------------------------------------------------
__global__ void __launch_bounds__(256)
beta_noise_kernel(const float* __restrict__ mcp, float* __restrict__ out,
                  uint32_t ka0, uint32_t ka1, uint32_t kb0, uint32_t kb1) {
  __shared__ float G[64];
  unsigned bc = blockIdx.y;
  if (threadIdx.x < 64)
    G[threadIdx.x] = mcp[bc * 64u + threadIdx.x] * 0.9f + 0.05f;
  __syncthreads();

  unsigned pix = blockIdx.x * 256u + threadIdx.x;
  unsigned y = pix >> 9, x = pix & 511u;

  // separable bicubic: m = wy^T * G * wx
  const float4* wx4 = reinterpret_cast<const float4*>(g_w[x]);
  float4 wxa = wx4[0], wxb = wx4[1];
  const float4* wy4 = reinterpret_cast<const float4*>(g_w[y]);
  float4 wya = wy4[0], wyb = wy4[1];
  float wyv[8] = {wya.x, wya.y, wya.z, wya.w, wyb.x, wyb.y, wyb.z, wyb.w};

  float m = 0.0f;
#pragma unroll
  for (int i = 0; i < 8; i++) {
    const float* gr = &G[i * 8];
    float gy = wxa.x * gr[0] + wxa.y * gr[1] + wxa.z * gr[2] + wxa.w * gr[3]
             + wxb.x * gr[4] + wxb.y * gr[5] + wxb.z * gr[6] + wxb.w * gr[7];
    m += wyv[i] * gy;
  }

  m = fminf(fmaxf(m, 0.05f), 0.95f);
  float t  = m * (1.0f - m);
  float sd = t - 1e-6f;
  float V_ = t / (sd * sd) - 1.0f;
  float Alpha = fmaxf(m * V_, 0.0f) + 1e-6f;          // always > 1 here
  float Beta  = fmaxf((1.0f - m) * V_, 0.0f) + 1e-6f; // always > 1 here

  unsigned e = bc * PIX_PER_IMG + pix;

  // MT constants for both gammas (boost branch provably dead: alpha >= 1.0027)
  float da = Alpha - (1.0f / 3.0f);
  float ca = (1.0f / 3.0f) / sqrtf(da);
  float db = Beta - (1.0f / 3.0f);
  float cb = (1.0f / 3.0f) / sqrtf(db);

  // -------- interleaved straight-line fast paths for gamma A and gamma B ----
  // key chain: ek = TF(K,(0,e)); kc = TF(ek,(0,0)) [== split(ek)[0]];
  // first iteration uses xk = TF(kc,(0,1)), Uk = TF(kc,(0,2));
  // first normal draw uses sub = TF(xk,(0,1)).
  U2 eka = tf2x32(ka0, ka1, 0u, e);
  U2 ekb = tf2x32(kb0, kb1, 0u, e);
  U2 kca = tf2x32(eka.a, eka.b, 0u, 0u);
  U2 kcb = tf2x32(ekb.a, ekb.b, 0u, 0u);
  U2 xka = tf2x32(kca.a, kca.b, 0u, 1u);
  U2 xkb = tf2x32(kcb.a, kcb.b, 0u, 1u);
  U2 Uka = tf2x32(kca.a, kca.b, 0u, 2u);
  U2 Ukb = tf2x32(kcb.a, kcb.b, 0u, 2u);
  U2 sba = tf2x32(xka.a, xka.b, 0u, 1u);
  U2 sbb = tf2x32(xkb.a, xkb.b, 0u, 1u);

  float xa = normal_from_key(sba.a, sba.b);
  float xb = normal_from_key(sbb.a, sbb.b);
  float va = 1.0f + ca * xa;
  float vb = 1.0f + cb * xb;
  float Xa = xa * xa, Xb = xb * xb;
  float Va = (va * va) * va;
  float Vb = (vb * vb) * vb;
  float Ua = u01_from_bits(bits_scalar(Uka.a, Uka.b));
  float Ub = u01_from_bits(bits_scalar(Ukb.a, Ukb.b));

  // accept test (NaN-safe: va<=0 forces slow path before V is used)
  bool ok_a = (va > 0.0f) &&
              !((Ua >= 1.0f - 0.0331f * (Xa * Xa)) &&
                (logf(Ua) >= 0.5f * Xa + da * (1.0f - Va + logf(Va))));
  bool ok_b = (vb > 0.0f) &&
              !((Ub >= 1.0f - 0.0331f * (Xb * Xb)) &&
                (logf(Ub) >= 0.5f * Xb + db * (1.0f - Vb + logf(Vb))));

  if (!ok_a) Va = gamma_slow(kca.a, kca.b, da, ca);
  if (!ok_b) Vb = gamma_slow(kcb.a, kcb.b, db, cb);

  float lga = logf(da) + logf(Va);
  float lgb = logf(db) + logf(Vb);

  // beta = exp(lga-mx)/(exp(lga-mx)+exp(lgb-mx))
  float mx = fmaxf(lga, lgb);
  float ga = expf(lga - mx);
  float gb = expf(lgb - mx);
  out[e] = ga / (ga + gb);
}

// ---------------------------------------------------------------------------
extern "C" void kernel_launch(void* const* d_in, const int* in_sizes, int n_in,
                              void* d_out, int out_size) {
  // find mean_control_points by size (32*3*8*8 = 6144)
  const float* mcp = (const float*)d_in[1];
  for (int i = 0; i < n_in; i++)
    if (in_sizes[i] == 6144) { mcp = (const float*)d_in[i]; break; }

  // root key = threefry_seed(1234) = (0, 1234); key_a, key_b = split(root)
  U2 ka = tf2x32(0u, 1234u, 0u, 0u);
  U2 kb = tf2x32(0u, 1234u, 0u, 1u);

  weights_kernel<<<1, 512>>>();
  dim3 grid(PIX_PER_IMG / 256, B_ * C_);
  beta_noise_kernel<<<grid, 256>>>(mcp, (float*)d_out,
                                   ka.a, ka.b, kb.a, kb.b);
}

// round 5
// speedup vs baseline: 1.1505x; 1.1505x over previous
#include <cuda_runtime.h>
#include <stdint.h>

// ============================================================================
// ControlPointBetaNoise — exact re-implementation of the JAX reference.
// R4: inline continuation loops (no CALL, no first-attempt replay), lazy
// advancement of rejection-only keys (nk/nxt). Fast path = 14 threefry evals
// per element; each retry iteration = 6. logf(V) reused between accept test
// and loggamma value; final softmax folded to a single expf.
// ============================================================================

static const unsigned B_ = 32, C_ = 3, H_ = 512, W_ = 512;
static const unsigned PIX_PER_IMG = H_ * W_;              // 262144

struct U2 { uint32_t a, b; };

__host__ __device__ __forceinline__ uint32_t rotl32(uint32_t x, int r) {
#ifdef __CUDA_ARCH__
  return __funnelshift_l(x, x, r);
#else
  return (x << r) | (x >> (32 - r));
#endif
}

// threefry2x32, 20 rounds — matches jax._src.prng.threefry2x32 exactly.
__host__ __device__ __forceinline__ U2 tf2x32(uint32_t k0, uint32_t k1,
                                              uint32_t x0, uint32_t x1) {
  uint32_t ks2 = k0 ^ k1 ^ 0x1BD11BDAu;
  x0 += k0; x1 += k1;
#define TF_RND(r) { x0 += x1; x1 = rotl32(x1, (r)); x1 ^= x0; }
  TF_RND(13) TF_RND(15) TF_RND(26) TF_RND(6)
  x0 += k1;  x1 += ks2 + 1u;
  TF_RND(17) TF_RND(29) TF_RND(16) TF_RND(24)
  x0 += ks2; x1 += k0 + 2u;
  TF_RND(13) TF_RND(15) TF_RND(26) TF_RND(6)
  x0 += k0;  x1 += k1 + 3u;
  TF_RND(17) TF_RND(29) TF_RND(16) TF_RND(24)
  x0 += k1;  x1 += ks2 + 4u;
  TF_RND(13) TF_RND(15) TF_RND(26) TF_RND(6)
  x0 += ks2; x1 += k0 + 5u;
#undef TF_RND
  return U2{x0, x1};
}

// scalar-shape random_bits(key, 32, ())  [partitionable threefry]
__device__ __forceinline__ uint32_t bits_scalar(uint32_t k0, uint32_t k1) {
  U2 r = tf2x32(k0, k1, 0u, 0u);
  return r.a ^ r.b;
}

// uniform [0,1): bitcast((bits>>9)|0x3f800000) - 1.0  (matches jax._uniform)
__device__ __forceinline__ float u01_from_bits(uint32_t bits) {
  return __uint_as_float((bits >> 9) | 0x3F800000u) - 1.0f;
}

// XLA f32 erf_inv (Giles polynomial) — what lax.erf_inv lowers to.
__device__ __forceinline__ float erfinv_f32(float x) {
  float w = -log1pf(-x * x);
  float p;
  if (w < 5.0f) {
    w -= 2.5f;
    p = 2.81022636e-08f;
    p = fmaf(p, w, 3.43273939e-07f);
    p = fmaf(p, w, -3.5233877e-06f);
    p = fmaf(p, w, -4.39150654e-06f);
    p = fmaf(p, w, 0.00021858087f);
    p = fmaf(p, w, -0.00125372503f);
    p = fmaf(p, w, -0.00417768164f);
    p = fmaf(p, w, 0.246640727f);
    p = fmaf(p, w, 1.50140941f);
  } else {
    w = sqrtf(w) - 3.0f;
    p = -0.000200214257f;
    p = fmaf(p, w, 0.000100950558f);
    p = fmaf(p, w, 0.00134934322f);
    p = fmaf(p, w, -0.00367342844f);
    p = fmaf(p, w, 0.00573950773f);
    p = fmaf(p, w, -0.0076224613f);
    p = fmaf(p, w, 0.00943887047f);
    p = fmaf(p, w, 1.00167406f);
    p = fmaf(p, w, 2.83297682f);
  }
  return p * x;
}

// jax.random.normal: u = uniform(key, lo=nextafter(-1,0), hi=1); sqrt(2)*erfinv(u)
__device__ __forceinline__ float normal_from_key(uint32_t k0, uint32_t k1) {
  uint32_t bits = bits_scalar(k0, k1);
  float f = u01_from_bits(bits);
  const float LO = __uint_as_float(0xBF7FFFFFu);  // nextafter(-1,0)
  float u = fmaxf(LO, f * 2.0f + LO);
  return 1.41421356237f * erfinv_f32(u);
}

// ---------------------------------------------------------------------------
// Bicubic weight table: jax.image.resize "bicubic" (Keys a=-0.5, renormalized,
// half-pixel sampling). Identical for H and W (8 -> 512).
// ---------------------------------------------------------------------------
__device__ float g_w[512][8];

__global__ void weights_kernel() {
  int j = threadIdx.x;  // 0..511
  float s = (j + 0.5f) * (1.0f / 64.0f) - 0.5f;
  float w[8]; float sum = 0.0f;
#pragma unroll
  for (int i = 0; i < 8; i++) {
    float x = fabsf(s - (float)i);
    float out = ((1.5f * x - 2.5f) * x) * x + 1.0f;
    if (x >= 1.0f) out = ((-0.5f * x + 2.5f) * x - 4.0f) * x + 2.0f;
    if (x >= 2.0f) out = 0.0f;
    w[i] = out; sum += out;
  }
#pragma unroll
  for (int i = 0; i < 8; i++) g_w[j][i] = w[i] / sum;
}

// ---------------------------------------------------------------------------
// Marsaglia–Tsang continuation loop: resumes from an already-computed first
// attempt (outer key kl, inner key xk, draw x/v, uniform U). Lazily advances
// keys only when a retry actually happens — no replayed threefry work.
// Returns log(V) of the accepted draw.
// ---------------------------------------------------------------------------
__device__ __forceinline__ float mt_finish(uint32_t kl0, uint32_t kl1,
                                           uint32_t xk0, uint32_t xk1,
                                           float x, float v, float U,
                                           float d, float c) {
  for (;;) {
    // inner rejection: redraw normal until v > 0 (advance inner key lazily)
    while (v <= 0.0f) {
      U2 nxt = tf2x32(xk0, xk1, 0u, 0u);
      xk0 = nxt.a; xk1 = nxt.b;
      U2 sub = tf2x32(xk0, xk1, 0u, 1u);
      x = normal_from_key(sub.a, sub.b);
      v = fmaf(c, x, 1.0f);
    }
    float X = x * x;
    float V = (v * v) * v;
    float lV = logf(V);
    bool rej = (U >= 1.0f - 0.0331f * (X * X)) &&
               (logf(U) >= 0.5f * X + d * (1.0f - V + lV));
    if (!rej) return lV;
    // outer rejection: advance outer key lazily, draw a fresh attempt
    U2 nk = tf2x32(kl0, kl1, 0u, 0u);
    kl0 = nk.a; kl1 = nk.b;
    U2 xk = tf2x32(kl0, kl1, 0u, 1u);
    xk0 = xk.a; xk1 = xk.b;
    U2 Uk = tf2x32(kl0, kl1, 0u, 2u);
    U2 sub = tf2x32(xk0, xk1, 0u, 1u);
    x = normal_from_key(sub.a, sub.b);
    v = fmaf(c, x, 1.0f);
    U = u01_from_bits(bits_scalar(Uk.a, Uk.b));
  }
}

// ---------------------------------------------------------------------------
// Main kernel: one thread per output pixel.
// ---------------------------------------------------------------------------
__global__ void __launch_bounds__(256)
beta_noise_kernel(const float* __restrict__ mcp, float* __restrict__ out,
                  uint32_t ka0, uint32_t ka1, uint32_t kb0, uint32_t kb1) {
  __shared__ float G[64];
  unsigned bc = blockIdx.y;
  if (threadIdx.x < 64)
    G[threadIdx.x] = mcp[bc * 64u + threadIdx.x] * 0.9f + 0.05f;
  __syncthreads();

  unsigned pix = blockIdx.x * 256u + threadIdx.x;
  unsigned y = pix >> 9, x = pix & 511u;

  // separable bicubic: m = wy^T * G * wx
  const float4* wx4 = reinterpret_cast<const float4*>(g_w[x]);
  float4 wxa = wx4[0], wxb = wx4[1];
  const float4* wy4 = reinterpret_cast<const float4*>(g_w[y]);
  float4 wya = wy4[0], wyb = wy4[1];
  float wyv[8] = {wya.x, wya.y, wya.z, wya.w, wyb.x, wyb.y, wyb.z, wyb.w};

  float m = 0.0f;
#pragma unroll
  for (int i = 0; i < 8; i++) {
    const float* gr = &G[i * 8];
    float gy = wxa.x * gr[0] + wxa.y * gr[1] + wxa.z * gr[2] + wxa.w * gr[3]
             + wxb.x * gr[4] + wxb.y * gr[5] + wxb.z * gr[6] + wxb.w * gr[7];
    m += wyv[i] * gy;
  }

  m = fminf(fmaxf(m, 0.05f), 0.95f);
  float t  = m * (1.0f - m);
  float sd = t - 1e-6f;
  float V_ = t / (sd * sd) - 1.0f;
  float Alpha = fmaxf(m * V_, 0.0f) + 1e-6f;          // always >= 1.0027
  float Beta  = fmaxf((1.0f - m) * V_, 0.0f) + 1e-6f; // always >= 1.0027

  // MT constants (boost branch provably dead: alpha >= 1)
  float da = Alpha - (1.0f / 3.0f);
  float ca = (1.0f / 3.0f) / sqrtf(da);
  float db = Beta - (1.0f / 3.0f);
  float cb = (1.0f / 3.0f) / sqrtf(db);

  unsigned e = bc * PIX_PER_IMG + pix;

  // -------- first attempts for gamma A and gamma B, interleaved for ILP ----
  // key chain: ek = TF(K,(0,e)); kc = split(ek)[0] = TF(ek,(0,0));
  // xk = TF(kc,(0,1)); Uk = TF(kc,(0,2)); sub = TF(xk,(0,1)).
  U2 eka = tf2x32(ka0, ka1, 0u, e);
  U2 ekb = tf2x32(kb0, kb1, 0u, e);
  U2 kca = tf2x32(eka.a, eka.b, 0u, 0u);
  U2 kcb = tf2x32(ekb.a, ekb.b, 0u, 0u);
  U2 xka = tf2x32(kca.a, kca.b, 0u, 1u);
  U2 xkb = tf2x32(kcb.a, kcb.b, 0u, 1u);
  U2 Uka = tf2x32(kca.a, kca.b, 0u, 2u);
  U2 Ukb = tf2x32(kcb.a, kcb.b, 0u, 2u);
  U2 sba = tf2x32(xka.a, xka.b, 0u, 1u);
  U2 sbb = tf2x32(xkb.a, xkb.b, 0u, 1u);

  float xa = normal_from_key(sba.a, sba.b);
  float xb = normal_from_key(sbb.a, sbb.b);
  float va = fmaf(ca, xa, 1.0f);
  float vb = fmaf(cb, xb, 1.0f);
  float Ua = u01_from_bits(bits_scalar(Uka.a, Uka.b));
  float Ub = u01_from_bits(bits_scalar(Ukb.a, Ukb.b));

  // -------- continuation loops (retries only; warp-wide cost 6 TF/iter) ----
  float logVa = mt_finish(kca.a, kca.b, xka.a, xka.b, xa, va, Ua, da, ca);
  float logVb = mt_finish(kcb.a, kcb.b, xkb.a, xkb.b, xb, vb, Ub, db, cb);

  float lga = logf(da) + logVa;
  float lgb = logf(db) + logVb;

  // beta = exp(lga-mx)/(exp(lga-mx)+exp(lgb-mx)) == 1/(1+exp(lgb-lga))
  out[e] = 1.0f / (1.0f + expf(lgb - lga));
}

// ---------------------------------------------------------------------------
extern "C" void kernel_launch(void* const* d_in, const int* in_sizes, int n_in,
                              void* d_out, int out_size) {
  // find mean_control_points by size (32*3*8*8 = 6144)
  const float* mcp = (const float*)d_in[1];
  for (int i = 0; i < n_in; i++)
    if (in_sizes[i] == 6144) { mcp = (const float*)d_in[i]; break; }

  // root key = threefry_seed(1234) = (0, 1234); key_a, key_b = split(root)
  U2 ka = tf2x32(0u, 1234u, 0u, 0u);
  U2 kb = tf2x32(0u, 1234u, 0u, 1u);

  weights_kernel<<<1, 512>>>();
  dim3 grid(PIX_PER_IMG / 256, B_ * C_);
  beta_noise_kernel<<<grid, 256>>>(mcp, (float*)d_out,
                                   ka.a, ka.b, kb.a, kb.b);
}